// round 1
// baseline (speedup 1.0000x reference)
#include <cuda_runtime.h>
#include <math.h>

#define B_    4096
#define C_    6
#define L_    1024
#define MID_  512
#define HID_  512
#define OUT_  256
#define K_    5
#define NBIG  5632            /* 2*K*MID + HID = 2560+2560+512 */
#define MROWS (B_ * C_)       /* 24576 */

/* Scratch (static __device__ globals — no runtime allocation) */
__device__ float g_Wbig[(size_t)L_ * NBIG];          /* 23 MB  */
__device__ float g_Y[(size_t)MROWS * NBIG];          /* 554 MB */

/* ------------------------------------------------------------------ */
/* Pack aW1 (K,L,MID), aW2 (K,L,MID), gW1 (L,HID) into Wbig (L, NBIG) */
/* ------------------------------------------------------------------ */
__global__ void pack_kernel(const float* __restrict__ aW1,
                            const float* __restrict__ aW2,
                            const float* __restrict__ gW1) {
    int idx = blockIdx.x * blockDim.x + threadIdx.x;
    if (idx >= L_ * NBIG) return;
    int l = idx / NBIG;
    int n = idx - l * NBIG;
    float v;
    if (n < K_ * MID_) {
        int k = n >> 9, m = n & 511;
        v = aW1[((size_t)k * L_ + l) * MID_ + m];
    } else if (n < 2 * K_ * MID_) {
        int nn = n - K_ * MID_;
        int k = nn >> 9, m = nn & 511;
        v = aW2[((size_t)k * L_ + l) * MID_ + m];
    } else {
        v = gW1[l * HID_ + (n - 2 * K_ * MID_)];
    }
    g_Wbig[idx] = v;
}

/* ------------------------------------------------------------------ */
/* SGEMM: g_Y(24576 x 5632) = X(24576 x 1024) * g_Wbig(1024 x 5632)   */
/* 128x128x16 tile, 256 threads, 8x8 per-thread micro-tile            */
/* ------------------------------------------------------------------ */
#define BM 128
#define BN 128
#define BK 16

__global__ void __launch_bounds__(256, 2) sgemm_kernel(const float* __restrict__ X) {
    __shared__ float As[BK][BM];
    __shared__ float Bs[BK][BN];

    const int bx = blockIdx.x;   /* N tile: 0..43  */
    const int by = blockIdx.y;   /* M tile: 0..191 */
    const int tid = threadIdx.x;
    const int tx = tid & 15;
    const int ty = tid >> 4;

    const int a_row = tid >> 2;          /* 0..63  */
    const int a_col = (tid & 3) << 2;    /* 0,4,8,12 */
    const int b_row = tid >> 5;          /* 0..7   */
    const int b_col = (tid & 31) << 2;   /* 0..124 */

    const float* Ab = X + (size_t)(by * BM) * L_;
    const float* Bb = g_Wbig + bx * BN;

    float acc[8][8];
#pragma unroll
    for (int i = 0; i < 8; i++)
#pragma unroll
        for (int j = 0; j < 8; j++) acc[i][j] = 0.f;

    for (int k0 = 0; k0 < L_; k0 += BK) {
#pragma unroll
        for (int i = 0; i < 2; i++) {
            int r = a_row + i * 64;
            float4 v = *(const float4*)(Ab + (size_t)r * L_ + k0 + a_col);
            As[a_col + 0][r] = v.x;
            As[a_col + 1][r] = v.y;
            As[a_col + 2][r] = v.z;
            As[a_col + 3][r] = v.w;
        }
#pragma unroll
        for (int i = 0; i < 2; i++) {
            int r = b_row + i * 8;
            *(float4*)&Bs[r][b_col] =
                *(const float4*)(Bb + (size_t)(k0 + r) * NBIG + b_col);
        }
        __syncthreads();

#pragma unroll
        for (int kk = 0; kk < BK; kk++) {
            float4 a0 = *(const float4*)&As[kk][ty * 8];
            float4 a1 = *(const float4*)&As[kk][ty * 8 + 4];
            float4 b0 = *(const float4*)&Bs[kk][tx * 8];
            float4 b1 = *(const float4*)&Bs[kk][tx * 8 + 4];
            float ar[8] = {a0.x, a0.y, a0.z, a0.w, a1.x, a1.y, a1.z, a1.w};
            float br[8] = {b0.x, b0.y, b0.z, b0.w, b1.x, b1.y, b1.z, b1.w};
#pragma unroll
            for (int i = 0; i < 8; i++)
#pragma unroll
                for (int j = 0; j < 8; j++) acc[i][j] += ar[i] * br[j];
        }
        __syncthreads();
    }

    float* Cp = g_Y + (size_t)(by * BM + ty * 8) * NBIG + bx * BN + tx * 8;
#pragma unroll
    for (int i = 0; i < 8; i++) {
#pragma unroll
        for (int j = 0; j < 8; j += 4) {
            float4 v = make_float4(acc[i][j], acc[i][j + 1], acc[i][j + 2], acc[i][j + 3]);
            *(float4*)(Cp + (size_t)i * NBIG + j) = v;
        }
    }
}

/* ------------------------------------------------------------------ */
/* Fused per-batch tail: scores -> softmax -> A -> GC1 -> GC2 -> out  */
/* One CTA per batch element b. 256 threads.                          */
/* ------------------------------------------------------------------ */
__global__ void __launch_bounds__(256) attn_kernel(
    const float* __restrict__ ab1, const float* __restrict__ ab2,
    const float* __restrict__ linW, const float* __restrict__ linb,
    const float* __restrict__ gb1, const float* __restrict__ gb2,
    const float* __restrict__ gW2, const float* __restrict__ prelu_a,
    const float* __restrict__ bn1g, const float* __restrict__ bn1b,
    const float* __restrict__ bn1m, const float* __restrict__ bn1v,
    const float* __restrict__ bn2g, const float* __restrict__ bn2b,
    const float* __restrict__ bn2m, const float* __restrict__ bn2v,
    float* __restrict__ out) {
    const int b = blockIdx.x;
    const float* Yb = g_Y + (size_t)b * C_ * NBIG;

    __shared__ float s_sc[K_][C_][C_];
    __shared__ float s_A[C_][C_];
    __shared__ float s_xg[C_][HID_];
    __shared__ float s_h[C_][HID_];
    __shared__ float s_P[C_][HID_];

    const int tid = threadIdx.x;
    const int lane = tid & 31;
    const int w = tid >> 5;

    /* 1) attention logits: 180 warp-collective dot-512s (bias-corrected) */
    for (int idx = w; idx < K_ * C_ * C_; idx += 8) {
        int k = idx / 36;
        int r = idx - k * 36;
        int c = r / 6;
        int d = r - c * 6;
        const float* qp = Yb + c * NBIG + k * MID_;
        const float* kp = Yb + d * NBIG + K_ * MID_ + k * MID_;
        const float* p1 = ab1 + k * MID_;
        const float* p2 = ab2 + k * MID_;
        float acc = 0.f;
        for (int m = lane; m < MID_; m += 32)
            acc += (qp[m] + p1[m]) * (kp[m] + p2[m]);
#pragma unroll
        for (int o = 16; o; o >>= 1) acc += __shfl_xor_sync(0xffffffffu, acc, o);
        if (lane == 0) s_sc[k][c][d] = acc;
    }
    /* stage xg = (x@gW1)[b] while scores settle */
    for (int i = tid; i < C_ * HID_; i += 256) {
        int c = i >> 9, j = i & 511;
        s_xg[c][j] = Yb[c * NBIG + 2 * K_ * MID_ + j];
    }
    __syncthreads();

    /* 2) softmax over d (30 rows) */
    if (tid < K_ * C_) {
        int k = tid / 6, c = tid - (tid / 6) * 6;
        float mx = s_sc[k][c][0];
#pragma unroll
        for (int d = 1; d < 6; d++) mx = fmaxf(mx, s_sc[k][c][d]);
        float e[6], sum = 0.f;
#pragma unroll
        for (int d = 0; d < 6; d++) { e[d] = expf(s_sc[k][c][d] - mx); sum += e[d]; }
        float inv = 1.f / sum;
#pragma unroll
        for (int d = 0; d < 6; d++) s_sc[k][c][d] = e[d] * inv;
    }
    __syncthreads();

    /* 3) linear exchange: logits2[c][e] = cat[c,:] @ linW + linb */
    if (tid < 36) {
        int c = tid / 6, e = tid - (tid / 6) * 6;
        float acc = linb[e];
#pragma unroll
        for (int k = 0; k < K_; k++)
#pragma unroll
            for (int d = 0; d < 6; d++)
                acc += s_sc[k][c][d] * linW[(k * 6 + d) * 6 + e];
        s_A[c][e] = acc;
    }
    __syncthreads();

    /* 4) softmax over e -> adjacency A (6x6) */
    if (tid < 6) {
        float mx = s_A[tid][0];
#pragma unroll
        for (int e = 1; e < 6; e++) mx = fmaxf(mx, s_A[tid][e]);
        float ev[6], sum = 0.f;
#pragma unroll
        for (int e = 0; e < 6; e++) { ev[e] = expf(s_A[tid][e] - mx); sum += ev[e]; }
        float inv = 1.f / sum;
#pragma unroll
        for (int e = 0; e < 6; e++) s_A[tid][e] = ev[e] * inv;
    }
    __syncthreads();

    /* 5) GC1: h = A @ xg + gb1, PReLU, BN1 */
    const float pa = prelu_a[0];
    for (int i = tid; i < C_ * HID_; i += 256) {
        int c = i >> 9, j = i & 511;
        float acc = gb1[j];
#pragma unroll
        for (int d = 0; d < 6; d++) acc += s_A[c][d] * s_xg[d][j];
        acc = acc >= 0.f ? acc : pa * acc;
        float inv = bn1g[c] * (1.f / sqrtf(bn1v[c] + 1e-5f));
        s_h[c][j] = (acc - bn1m[c]) * inv + bn1b[c];
    }
    __syncthreads();

    /* 6) P = A @ h */
    for (int i = tid; i < C_ * HID_; i += 256) {
        int c = i >> 9, j = i & 511;
        float acc = 0.f;
#pragma unroll
        for (int d = 0; d < 6; d++) acc += s_A[c][d] * s_h[d][j];
        s_P[c][j] = acc;
    }
    __syncthreads();

    /* 7) out = P @ gW2 + gb2, BN2.  thread tid owns output column o. */
    {
        const int o = tid; /* OUT_ == 256 == blockDim */
        float acc[6];
#pragma unroll
        for (int c = 0; c < 6; c++) acc[c] = gb2[o];
        const float* gp = gW2 + o;
#pragma unroll 8
        for (int j = 0; j < HID_; j++) {
            float wv = gp[(size_t)j * OUT_];
#pragma unroll
            for (int c = 0; c < 6; c++) acc[c] += s_P[c][j] * wv;
        }
#pragma unroll
        for (int c = 0; c < 6; c++) {
            float inv = bn2g[c] * (1.f / sqrtf(bn2v[c] + 1e-5f));
            float v = (acc[c] - bn2m[c]) * inv + bn2b[c];
            out[((size_t)b * C_ + c) * OUT_ + o] = v;
        }
    }
}

/* ------------------------------------------------------------------ */
extern "C" void kernel_launch(void* const* d_in, const int* in_sizes, int n_in,
                              void* d_out, int out_size) {
    const float* x       = (const float*)d_in[0];
    const float* aW1     = (const float*)d_in[1];
    const float* ab1     = (const float*)d_in[2];
    const float* aW2     = (const float*)d_in[3];
    const float* ab2     = (const float*)d_in[4];
    const float* linW    = (const float*)d_in[5];
    const float* linb    = (const float*)d_in[6];
    const float* gW1     = (const float*)d_in[7];
    const float* gb1     = (const float*)d_in[8];
    const float* gW2     = (const float*)d_in[9];
    const float* gb2     = (const float*)d_in[10];
    const float* prelu_a = (const float*)d_in[11];
    const float* bn1g    = (const float*)d_in[12];
    const float* bn1b    = (const float*)d_in[13];
    const float* bn1m    = (const float*)d_in[14];
    const float* bn1v    = (const float*)d_in[15];
    const float* bn2g    = (const float*)d_in[16];
    const float* bn2b    = (const float*)d_in[17];
    const float* bn2m    = (const float*)d_in[18];
    const float* bn2v    = (const float*)d_in[19];
    float* out = (float*)d_out;

    int total = L_ * NBIG;
    pack_kernel<<<(total + 255) / 256, 256>>>(aW1, aW2, gW1);

    dim3 g(NBIG / BN, MROWS / BM);
    sgemm_kernel<<<g, 256>>>(x);

    attn_kernel<<<B_, 256>>>(ab1, ab2, linW, linb, gb1, gb2, gW2, prelu_a,
                             bn1g, bn1b, bn1m, bn1v, bn2g, bn2b, bn2m, bn2v,
                             out);
}

// round 3
// speedup vs baseline: 1.4431x; 1.4431x over previous
#include <cuda_runtime.h>
#include <math.h>
#include <stdint.h>

#define B_    4096
#define C_    6
#define L_    1024
#define MID_  512
#define HID_  512
#define OUT_  256
#define K_    5
#define NBIG  5632            /* 2*K*MID + HID */
#define MROWS (B_ * C_)       /* 24576 */
#define KP    3072            /* 3xTF32 augmented K */
#define KCS   384             /* KP/8 k8-chunks */

/* GEMM tiling */
#define TM 128
#define TN 256
#define NSTG 96               /* KP/32 stages */
#define ASTG_BYTES 16384      /* 4 kc * 8 mt * 512B */
#define BSTG_BYTES 32768      /* 4 kc * 16 nt * 512B */
#define STG_BYTES  49152
#define SMEM_TOTAL (4 * STG_BYTES)   /* 196608 */

/* Scratch: fragment-ready packed operands + Y */
__device__ float g_Ap[(size_t)MROWS * KP];   /* [M/16][384][32][4] */
__device__ float g_Bp[(size_t)NBIG * KP];    /* [N/16][384][32][4] */
__device__ float g_Y[(size_t)MROWS * NBIG];

__device__ __forceinline__ uint32_t smem_u32(const void* p) {
    uint32_t a;
    asm("{ .reg .u64 t; cvta.to.shared.u64 t, %1; cvt.u32.u64 %0, t; }" : "=r"(a) : "l"(p));
    return a;
}
__device__ __forceinline__ void cpa16(uint32_t s, const void* g) {
    asm volatile("cp.async.cg.shared.global [%0], [%1], 16;" :: "r"(s), "l"(g) : "memory");
}
__device__ __forceinline__ void lds128(uint32_t* r, uint32_t a) {
    asm volatile("ld.shared.v4.b32 {%0,%1,%2,%3}, [%4];"
                 : "=r"(r[0]), "=r"(r[1]), "=r"(r[2]), "=r"(r[3]) : "r"(a));
}
__device__ __forceinline__ void mma_tf32(float* c, const uint32_t* a, uint32_t b0, uint32_t b1) {
    asm volatile(
        "mma.sync.aligned.m16n8k8.row.col.f32.tf32.tf32.f32 "
        "{%0,%1,%2,%3}, {%4,%5,%6,%7}, {%8,%9}, {%0,%1,%2,%3};"
        : "+f"(c[0]), "+f"(c[1]), "+f"(c[2]), "+f"(c[3])
        : "r"(a[0]), "r"(a[1]), "r"(a[2]), "r"(a[3]), "r"(b0), "r"(b1));
}
__device__ __forceinline__ float tf32_rna(float x) {
    uint32_t u;
    asm("cvt.rna.tf32.f32 %0, %1;" : "=r"(u) : "f"(x));
    return __uint_as_float(u);
}

/* ------------------------------------------------------------------ */
/* packA: one thread per 16B chunk of g_Ap.                           */
/* chunk (mt, kc, lane) holds m16n8k8 A-frag regs {a0,a1,a2,a3}:      */
/*   (r,k) (r+8,k) (r,k+4) (r+8,k+4); r=mt*16+ln/4, k=kc*8+ln%4       */
/* aug-k regions: [0,1k)=hi  [1k,2k)=lo  [2k,3k)=hi                   */
/* ------------------------------------------------------------------ */
__global__ void packA_kernel(const float* __restrict__ X) {
    int cid = blockIdx.x * 256 + threadIdx.x;          /* < 18,874,368 */
    int ln = cid & 31;
    int b = cid >> 5;
    int kc = b % KCS;
    int mt = b / KCS;
    int p = kc >> 7;                                    /* region 0/1/2 */
    int l0 = (kc & 127) * 8 + (ln & 3);
    int r0 = mt * 16 + (ln >> 2);
    float x00 = X[(size_t)r0 * L_ + l0];
    float x10 = X[(size_t)(r0 + 8) * L_ + l0];
    float x01 = X[(size_t)r0 * L_ + l0 + 4];
    float x11 = X[(size_t)(r0 + 8) * L_ + l0 + 4];
    float4 v;
    if (p == 1) {
        v.x = tf32_rna(x00 - tf32_rna(x00));
        v.y = tf32_rna(x10 - tf32_rna(x10));
        v.z = tf32_rna(x01 - tf32_rna(x01));
        v.w = tf32_rna(x11 - tf32_rna(x11));
    } else {
        v.x = tf32_rna(x00); v.y = tf32_rna(x10);
        v.z = tf32_rna(x01); v.w = tf32_rna(x11);
    }
    *(float4*)(g_Ap + (size_t)cid * 4) = v;
}

/* ------------------------------------------------------------------ */
/* packB: chunk (nt, kc, lane) holds {b0_n0, b1_n0, b0_n1, b1_n1}:    */
/*   n0=nt*16+ln/4, n1=n0+8, k=kc*8+ln%4 (+4 for b1)                  */
/* aug-k regions: [0,1k)=hi  [1k,2k)=hi  [2k,3k)=lo                   */
/* ------------------------------------------------------------------ */
__device__ __forceinline__ float fetchW(const float* aW1, const float* aW2,
                                        const float* gW1, int l, int n) {
    if (n < K_ * MID_) {
        return aW1[((size_t)(n >> 9) * L_ + l) * MID_ + (n & 511)];
    } else if (n < 2 * K_ * MID_) {
        int nn = n - K_ * MID_;
        return aW2[((size_t)(nn >> 9) * L_ + l) * MID_ + (nn & 511)];
    }
    return gW1[(size_t)l * HID_ + (n - 2 * K_ * MID_)];
}
__global__ void packB_kernel(const float* __restrict__ aW1,
                             const float* __restrict__ aW2,
                             const float* __restrict__ gW1) {
    int cid = blockIdx.x * 256 + threadIdx.x;          /* < 4,325,376 */
    int ln = cid & 31;
    int b = cid >> 5;
    int kc = b % KCS;
    int nt = b / KCS;
    int p = kc >> 7;
    int l0 = (kc & 127) * 8 + (ln & 3);
    int n0 = nt * 16 + (ln >> 2);
    float w00 = fetchW(aW1, aW2, gW1, l0,     n0);
    float w10 = fetchW(aW1, aW2, gW1, l0 + 4, n0);
    float w01 = fetchW(aW1, aW2, gW1, l0,     n0 + 8);
    float w11 = fetchW(aW1, aW2, gW1, l0 + 4, n0 + 8);
    float4 v;
    if (p == 2) {
        v.x = tf32_rna(w00 - tf32_rna(w00));
        v.y = tf32_rna(w10 - tf32_rna(w10));
        v.z = tf32_rna(w01 - tf32_rna(w01));
        v.w = tf32_rna(w11 - tf32_rna(w11));
    } else {
        v.x = tf32_rna(w00); v.y = tf32_rna(w10);
        v.z = tf32_rna(w01); v.w = tf32_rna(w11);
    }
    *(float4*)(g_Bp + (size_t)cid * 4) = v;
}

/* ------------------------------------------------------------------ */
/* GEMM: Y(24576x5632) = Ap @ Bp^T  via mma.sync m16n8k8 tf32         */
/* CTA 128x256, 8 warps (2x4), warp tile 64x64, 4-stage cp.async      */
/* ------------------------------------------------------------------ */
struct IssueCtx { uint32_t sb; int mtB, ntB, tid; };

__device__ __forceinline__ void issue_stage(const IssueCtx& cx, int s) {
    uint32_t stBase = cx.sb + (s & 3) * STG_BYTES;
    int kc0 = s * 4;
#pragma unroll
    for (int i = 0; i < 4; i++) {                       /* A: 1024 chunks */
        int cid = cx.tid + i * 256;
        int ln = cid & 31, bb = cid >> 5;
        int kci = bb >> 3, mti = bb & 7;
        uint32_t sa = stBase + (uint32_t)(((kci * 8 + mti) * 32 + ln) * 16);
        const float* ga = g_Ap + (((size_t)(cx.mtB + mti) * KCS + kc0 + kci) * 32 + ln) * 4;
        cpa16(sa, ga);
    }
#pragma unroll
    for (int i = 0; i < 8; i++) {                       /* B: 2048 chunks */
        int cid = cx.tid + i * 256;
        int ln = cid & 31, bb = cid >> 5;
        int kci = bb >> 4, nti = bb & 15;
        uint32_t sb2 = stBase + ASTG_BYTES + (uint32_t)(((kci * 16 + nti) * 32 + ln) * 16);
        const float* gb = g_Bp + (((size_t)(cx.ntB + nti) * KCS + kc0 + kci) * 32 + ln) * 4;
        cpa16(sb2, gb);
    }
    asm volatile("cp.async.commit_group;" ::: "memory");
}

__global__ void __launch_bounds__(256, 1) gemm_kernel() {
    extern __shared__ char smem[];
    const uint32_t sb = smem_u32(smem);
    const int tid = threadIdx.x;
    const int lane = tid & 31;
    const int wid = tid >> 5;
    const int wm = wid & 1;        /* M half  */
    const int wn = wid >> 1;       /* N quarter */
    const int mtB = blockIdx.y * 8;
    const int ntB = blockIdx.x * 16;

    IssueCtx cx{sb, mtB, ntB, tid};

    float acc[4][8][4];
#pragma unroll
    for (int a = 0; a < 4; a++)
#pragma unroll
        for (int bq = 0; bq < 8; bq++)
#pragma unroll
            for (int c = 0; c < 4; c++) acc[a][bq][c] = 0.f;

    issue_stage(cx, 0);
    issue_stage(cx, 1);
    issue_stage(cx, 2);

    for (int s = 0; s < NSTG; s++) {
        asm volatile("cp.async.wait_group 2;" ::: "memory");
        __syncthreads();
        if (s + 3 < NSTG) issue_stage(cx, s + 3);
        else asm volatile("cp.async.commit_group;" ::: "memory");

        uint32_t stBase = sb + (s & 3) * STG_BYTES;
#pragma unroll
        for (int kc = 0; kc < 4; kc++) {
            uint32_t af[4][4], bf[4][4];
#pragma unroll
            for (int mi = 0; mi < 4; mi++)
                lds128(af[mi], stBase + (uint32_t)((((kc * 8) + wm * 4 + mi) * 32 + lane) * 16));
#pragma unroll
            for (int ni = 0; ni < 4; ni++)
                lds128(bf[ni], stBase + ASTG_BYTES +
                               (uint32_t)((((kc * 16) + wn * 4 + ni) * 32 + lane) * 16));
#pragma unroll
            for (int mi = 0; mi < 4; mi++)
#pragma unroll
                for (int ni = 0; ni < 4; ni++) {
                    mma_tf32(acc[mi][ni * 2],     af[mi], bf[ni][0], bf[ni][1]);
                    mma_tf32(acc[mi][ni * 2 + 1], af[mi], bf[ni][2], bf[ni][3]);
                }
        }
    }

    /* epilogue: c0,c1 -> (r, 2c..2c+1), c2,c3 -> (r+8, ...) */
    const int rBase = blockIdx.y * TM + wm * 64 + (lane >> 2);
    const int cBase = blockIdx.x * TN + wn * 64 + (lane & 3) * 2;
#pragma unroll
    for (int mi = 0; mi < 4; mi++) {
#pragma unroll
        for (int ni = 0; ni < 8; ni++) {
            int row = rBase + mi * 16;
            int col = cBase + ni * 8;
            *(float2*)(g_Y + (size_t)row * NBIG + col) =
                make_float2(acc[mi][ni][0], acc[mi][ni][1]);
            *(float2*)(g_Y + (size_t)(row + 8) * NBIG + col) =
                make_float2(acc[mi][ni][2], acc[mi][ni][3]);
        }
    }
}

/* ------------------------------------------------------------------ */
/* Fused per-batch tail (unchanged)                                   */
/* ------------------------------------------------------------------ */
__global__ void __launch_bounds__(256) attn_kernel(
    const float* __restrict__ ab1, const float* __restrict__ ab2,
    const float* __restrict__ linW, const float* __restrict__ linb,
    const float* __restrict__ gb1, const float* __restrict__ gb2,
    const float* __restrict__ gW2, const float* __restrict__ prelu_a,
    const float* __restrict__ bn1g, const float* __restrict__ bn1b,
    const float* __restrict__ bn1m, const float* __restrict__ bn1v,
    const float* __restrict__ bn2g, const float* __restrict__ bn2b,
    const float* __restrict__ bn2m, const float* __restrict__ bn2v,
    float* __restrict__ out) {
    const int b = blockIdx.x;
    const float* Yb = g_Y + (size_t)b * C_ * NBIG;

    __shared__ float s_sc[K_][C_][C_];
    __shared__ float s_A[C_][C_];
    __shared__ float s_xg[C_][HID_];
    __shared__ float s_h[C_][HID_];
    __shared__ float s_P[C_][HID_];

    const int tid = threadIdx.x;
    const int lane = tid & 31;
    const int w = tid >> 5;

    for (int idx = w; idx < K_ * C_ * C_; idx += 8) {
        int k = idx / 36;
        int r = idx - k * 36;
        int c = r / 6;
        int d = r - c * 6;
        const float* qp = Yb + c * NBIG + k * MID_;
        const float* kp = Yb + d * NBIG + K_ * MID_ + k * MID_;
        const float* p1 = ab1 + k * MID_;
        const float* p2 = ab2 + k * MID_;
        float acc = 0.f;
        for (int m = lane; m < MID_; m += 32)
            acc += (qp[m] + p1[m]) * (kp[m] + p2[m]);
#pragma unroll
        for (int o = 16; o; o >>= 1) acc += __shfl_xor_sync(0xffffffffu, acc, o);
        if (lane == 0) s_sc[k][c][d] = acc;
    }
    for (int i = tid; i < C_ * HID_; i += 256) {
        int c = i >> 9, j = i & 511;
        s_xg[c][j] = Yb[c * NBIG + 2 * K_ * MID_ + j];
    }
    __syncthreads();

    if (tid < K_ * C_) {
        int k = tid / 6, c = tid - (tid / 6) * 6;
        float mx = s_sc[k][c][0];
#pragma unroll
        for (int d = 1; d < 6; d++) mx = fmaxf(mx, s_sc[k][c][d]);
        float e[6], sum = 0.f;
#pragma unroll
        for (int d = 0; d < 6; d++) { e[d] = expf(s_sc[k][c][d] - mx); sum += e[d]; }
        float inv = 1.f / sum;
#pragma unroll
        for (int d = 0; d < 6; d++) s_sc[k][c][d] = e[d] * inv;
    }
    __syncthreads();

    if (tid < 36) {
        int c = tid / 6, e = tid - (tid / 6) * 6;
        float acc = linb[e];
#pragma unroll
        for (int k = 0; k < K_; k++)
#pragma unroll
            for (int d = 0; d < 6; d++)
                acc += s_sc[k][c][d] * linW[(k * 6 + d) * 6 + e];
        s_A[c][e] = acc;
    }
    __syncthreads();

    if (tid < 6) {
        float mx = s_A[tid][0];
#pragma unroll
        for (int e = 1; e < 6; e++) mx = fmaxf(mx, s_A[tid][e]);
        float ev[6], sum = 0.f;
#pragma unroll
        for (int e = 0; e < 6; e++) { ev[e] = expf(s_A[tid][e] - mx); sum += ev[e]; }
        float inv = 1.f / sum;
#pragma unroll
        for (int e = 0; e < 6; e++) s_A[tid][e] = ev[e] * inv;
    }
    __syncthreads();

    const float pa = prelu_a[0];
    for (int i = tid; i < C_ * HID_; i += 256) {
        int c = i >> 9, j = i & 511;
        float acc = gb1[j];
#pragma unroll
        for (int d = 0; d < 6; d++) acc += s_A[c][d] * s_xg[d][j];
        acc = acc >= 0.f ? acc : pa * acc;
        float inv = bn1g[c] * (1.f / sqrtf(bn1v[c] + 1e-5f));
        s_h[c][j] = (acc - bn1m[c]) * inv + bn1b[c];
    }
    __syncthreads();

    for (int i = tid; i < C_ * HID_; i += 256) {
        int c = i >> 9, j = i & 511;
        float acc = 0.f;
#pragma unroll
        for (int d = 0; d < 6; d++) acc += s_A[c][d] * s_h[d][j];
        s_P[c][j] = acc;
    }
    __syncthreads();

    {
        const int o = tid;
        float acc[6];
#pragma unroll
        for (int c = 0; c < 6; c++) acc[c] = gb2[o];
        const float* gp = gW2 + o;
#pragma unroll 8
        for (int j = 0; j < HID_; j++) {
            float wv = gp[(size_t)j * OUT_];
#pragma unroll
            for (int c = 0; c < 6; c++) acc[c] += s_P[c][j] * wv;
        }
#pragma unroll
        for (int c = 0; c < 6; c++) {
            float inv = bn2g[c] * (1.f / sqrtf(bn2v[c] + 1e-5f));
            float v = (acc[c] - bn2m[c]) * inv + bn2b[c];
            out[((size_t)b * C_ + c) * OUT_ + o] = v;
        }
    }
}

/* ------------------------------------------------------------------ */
extern "C" void kernel_launch(void* const* d_in, const int* in_sizes, int n_in,
                              void* d_out, int out_size) {
    const float* x       = (const float*)d_in[0];
    const float* aW1     = (const float*)d_in[1];
    const float* ab1     = (const float*)d_in[2];
    const float* aW2     = (const float*)d_in[3];
    const float* ab2     = (const float*)d_in[4];
    const float* linW    = (const float*)d_in[5];
    const float* linb    = (const float*)d_in[6];
    const float* gW1     = (const float*)d_in[7];
    const float* gb1     = (const float*)d_in[8];
    const float* gW2     = (const float*)d_in[9];
    const float* gb2     = (const float*)d_in[10];
    const float* prelu_a = (const float*)d_in[11];
    const float* bn1g    = (const float*)d_in[12];
    const float* bn1b    = (const float*)d_in[13];
    const float* bn1m    = (const float*)d_in[14];
    const float* bn1v    = (const float*)d_in[15];
    const float* bn2g    = (const float*)d_in[16];
    const float* bn2b    = (const float*)d_in[17];
    const float* bn2m    = (const float*)d_in[18];
    const float* bn2v    = (const float*)d_in[19];
    float* out = (float*)d_out;

    static bool attr_set = false;
    if (!attr_set) {
        cudaFuncSetAttribute(gemm_kernel,
                             cudaFuncAttributeMaxDynamicSharedMemorySize, SMEM_TOTAL);
        attr_set = true;
    }

    /* packs: 18,874,368 / 4,325,376 chunks, 1 thread each */
    packA_kernel<<<(MROWS / 16) * KCS * 32 / 256, 256>>>(x);
    packB_kernel<<<(NBIG / 16) * KCS * 32 / 256, 256>>>(aW1, aW2, gW1);

    dim3 grid(NBIG / TN, MROWS / TM);   /* 22 x 192 */
    gemm_kernel<<<grid, 256, SMEM_TOTAL>>>();

    attn_kernel<<<B_, 256>>>(ab1, ab2, linW, linb, gb1, gb2, gW2, prelu_a,
                             bn1g, bn1b, bn1m, bn1v, bn2g, bn2b, bn2m, bn2v,
                             out);
}

// round 4
// speedup vs baseline: 2.4139x; 1.6727x over previous
#include <cuda_runtime.h>
#include <cuda_fp16.h>
#include <math.h>
#include <stdint.h>

#define B_    4096
#define C_    6
#define L_    1024
#define MID_  512
#define HID_  512
#define OUT_  256
#define K_    5
#define NBIG  5632            /* 2*K*MID + HID */
#define MROWS (B_ * C_)       /* 24576 */
#define KP16  3072            /* 3xFP16 augmented K (fp16 elems) */
#define KC16  192             /* KP16/16 k16-chunks */

/* GEMM tiling: CTA 128x256, 8 warps 64x64, stage = 64 k */
#define TM 128
#define TN 256
#define NSTG 48
#define ASTG_BYTES 16384
#define STG_BYTES  49152
#define SMEM_TOTAL (4 * STG_BYTES)   /* 196608 */

/* Scratch */
__device__ uint4 g_Ah[(size_t)MROWS * KP16 / 8];   /* 151 MB fragment-ready fp16 */
__device__ uint4 g_Bh[(size_t)NBIG * KP16 / 8];    /*  35 MB */
__device__ float g_Y[(size_t)MROWS * NBIG];        /* 554 MB */

__device__ __forceinline__ uint32_t smem_u32(const void* p) {
    uint32_t a;
    asm("{ .reg .u64 t; cvta.to.shared.u64 t, %1; cvt.u32.u64 %0, t; }" : "=r"(a) : "l"(p));
    return a;
}
__device__ __forceinline__ void cpa16(uint32_t s, const void* g) {
    asm volatile("cp.async.cg.shared.global [%0], [%1], 16;" :: "r"(s), "l"(g) : "memory");
}
__device__ __forceinline__ void lds128(uint32_t* r, uint32_t a) {
    asm volatile("ld.shared.v4.b32 {%0,%1,%2,%3}, [%4];"
                 : "=r"(r[0]), "=r"(r[1]), "=r"(r[2]), "=r"(r[3]) : "r"(a));
}
__device__ __forceinline__ void mma_f16(float* c, const uint32_t* a, uint32_t b0, uint32_t b1) {
    asm volatile(
        "mma.sync.aligned.m16n8k16.row.col.f32.f16.f16.f32 "
        "{%0,%1,%2,%3}, {%4,%5,%6,%7}, {%8,%9}, {%0,%1,%2,%3};"
        : "+f"(c[0]), "+f"(c[1]), "+f"(c[2]), "+f"(c[3])
        : "r"(a[0]), "r"(a[1]), "r"(a[2]), "r"(a[3]), "r"(b0), "r"(b1));
}
__device__ __forceinline__ __half cvt_split(float x, bool lo) {
    __half hi = __float2half_rn(x);
    if (!lo) return hi;
    return __float2half_rn(x - __half2float(hi));
}

/* ------------------------------------------------------------------ */
/* packA: one thread per 16B chunk (8 fp16 = full m16n8k16 A-frag)    */
/* chunk (mt, kc16, lane): r0=mt*16+ln/4, k0=(ln%4)*2 within k16      */
/* order: (r0,k0)(r0,k0+1)(r0+8,k0)(r0+8,k0+1)(r0,k0+8)(r0,k0+9)      */
/*        (r0+8,k0+8)(r0+8,k0+9).  aug: kc [0,64)=hi [64,128)=lo      */
/*        [128,192)=hi                                                */
/* ------------------------------------------------------------------ */
__global__ void packA_kernel(const float* __restrict__ X) {
    int cid = blockIdx.x * 256 + threadIdx.x;      /* < 9,437,184 */
    int ln = cid & 31;
    int b = cid >> 5;
    int kc = b % KC16;
    int mt = b / KC16;
    bool lo = (kc >> 6) == 1;
    int l0 = (kc & 63) * 16 + (ln & 3) * 2;
    int r0 = mt * 16 + (ln >> 2);
    float2 x00 = *(const float2*)(X + (size_t)r0 * L_ + l0);
    float2 x10 = *(const float2*)(X + (size_t)(r0 + 8) * L_ + l0);
    float2 x01 = *(const float2*)(X + (size_t)r0 * L_ + l0 + 8);
    float2 x11 = *(const float2*)(X + (size_t)(r0 + 8) * L_ + l0 + 8);
    __half h[8];
    h[0] = cvt_split(x00.x, lo); h[1] = cvt_split(x00.y, lo);
    h[2] = cvt_split(x10.x, lo); h[3] = cvt_split(x10.y, lo);
    h[4] = cvt_split(x01.x, lo); h[5] = cvt_split(x01.y, lo);
    h[6] = cvt_split(x11.x, lo); h[7] = cvt_split(x11.y, lo);
    g_Ah[cid] = *(uint4*)h;
}

/* ------------------------------------------------------------------ */
/* packB: chunk (nt, kc16, lane) = two B-frags (n0, n1=n0+8)          */
/* order: (l0,n0)(l0+1,n0)(l0+8,n0)(l0+9,n0)(l0,n1)(l0+1,n1)          */
/*        (l0+8,n1)(l0+9,n1).  aug: [0,64)=hi [64,128)=hi [128,192)=lo*/
/* ------------------------------------------------------------------ */
__device__ __forceinline__ float fetchW(const float* aW1, const float* aW2,
                                        const float* gW1, int l, int n) {
    if (n < K_ * MID_) {
        return aW1[((size_t)(n >> 9) * L_ + l) * MID_ + (n & 511)];
    } else if (n < 2 * K_ * MID_) {
        int nn = n - K_ * MID_;
        return aW2[((size_t)(nn >> 9) * L_ + l) * MID_ + (nn & 511)];
    }
    return gW1[(size_t)l * HID_ + (n - 2 * K_ * MID_)];
}
__global__ void packB_kernel(const float* __restrict__ aW1,
                             const float* __restrict__ aW2,
                             const float* __restrict__ gW1) {
    int cid = blockIdx.x * 256 + threadIdx.x;      /* < 2,162,688 */
    int ln = cid & 31;
    int b = cid >> 5;
    int kc = b % KC16;
    int nt = b / KC16;
    bool lo = (kc >> 6) == 2;
    int l0 = (kc & 63) * 16 + (ln & 3) * 2;
    int n0 = nt * 16 + (ln >> 2);
    int n1 = n0 + 8;
    __half h[8];
    h[0] = cvt_split(fetchW(aW1, aW2, gW1, l0,     n0), lo);
    h[1] = cvt_split(fetchW(aW1, aW2, gW1, l0 + 1, n0), lo);
    h[2] = cvt_split(fetchW(aW1, aW2, gW1, l0 + 8, n0), lo);
    h[3] = cvt_split(fetchW(aW1, aW2, gW1, l0 + 9, n0), lo);
    h[4] = cvt_split(fetchW(aW1, aW2, gW1, l0,     n1), lo);
    h[5] = cvt_split(fetchW(aW1, aW2, gW1, l0 + 1, n1), lo);
    h[6] = cvt_split(fetchW(aW1, aW2, gW1, l0 + 8, n1), lo);
    h[7] = cvt_split(fetchW(aW1, aW2, gW1, l0 + 9, n1), lo);
    g_Bh[cid] = *(uint4*)h;
}

/* ------------------------------------------------------------------ */
/* GEMM: Y = Ah @ Bh^T, m16n8k16 fp16, 4-stage cp.async               */
/* ------------------------------------------------------------------ */
struct IssueCtx { uint32_t sb; int mtB, ntB, tid; };

__device__ __forceinline__ void issue_stage(const IssueCtx& cx, int s) {
    uint32_t stBase = cx.sb + (s & 3) * STG_BYTES;
    int kc0 = s * 4;
#pragma unroll
    for (int i = 0; i < 4; i++) {                  /* A: 1024 chunks */
        int cid = cx.tid + i * 256;
        int ln = cid & 31, bb = cid >> 5;
        int kci = bb >> 3, mti = bb & 7;
        uint32_t sa = stBase + (uint32_t)(((kci * 8 + mti) * 32 + ln) * 16);
        const uint4* ga = g_Ah + ((size_t)(cx.mtB + mti) * KC16 + kc0 + kci) * 32 + ln;
        cpa16(sa, ga);
    }
#pragma unroll
    for (int i = 0; i < 8; i++) {                  /* B: 2048 chunks */
        int cid = cx.tid + i * 256;
        int ln = cid & 31, bb = cid >> 5;
        int kci = bb >> 4, nti = bb & 15;
        uint32_t sb2 = stBase + ASTG_BYTES + (uint32_t)(((kci * 16 + nti) * 32 + ln) * 16);
        const uint4* gb = g_Bh + ((size_t)(cx.ntB + nti) * KC16 + kc0 + kci) * 32 + ln;
        cpa16(sb2, gb);
    }
    asm volatile("cp.async.commit_group;" ::: "memory");
}

__global__ void __launch_bounds__(256, 1) gemm_kernel() {
    extern __shared__ char smem[];
    const uint32_t sb = smem_u32(smem);
    const int tid = threadIdx.x;
    const int lane = tid & 31;
    const int wid = tid >> 5;
    const int wm = wid & 1;
    const int wn = wid >> 1;
    const int mtB = blockIdx.y * 8;
    const int ntB = blockIdx.x * 16;

    IssueCtx cx{sb, mtB, ntB, tid};

    float acc[4][8][4];
#pragma unroll
    for (int a = 0; a < 4; a++)
#pragma unroll
        for (int bq = 0; bq < 8; bq++)
#pragma unroll
            for (int c = 0; c < 4; c++) acc[a][bq][c] = 0.f;

    issue_stage(cx, 0);
    issue_stage(cx, 1);
    issue_stage(cx, 2);

    for (int s = 0; s < NSTG; s++) {
        asm volatile("cp.async.wait_group 2;" ::: "memory");
        __syncthreads();
        if (s + 3 < NSTG) issue_stage(cx, s + 3);
        else asm volatile("cp.async.commit_group;" ::: "memory");

        uint32_t stBase = sb + (s & 3) * STG_BYTES;
#pragma unroll
        for (int kc = 0; kc < 4; kc++) {
            uint32_t af[4][4], bf[4][4];
#pragma unroll
            for (int mi = 0; mi < 4; mi++)
                lds128(af[mi], stBase + (uint32_t)((((kc * 8) + wm * 4 + mi) * 32 + lane) * 16));
#pragma unroll
            for (int ni = 0; ni < 4; ni++)
                lds128(bf[ni], stBase + ASTG_BYTES +
                               (uint32_t)((((kc * 16) + wn * 4 + ni) * 32 + lane) * 16));
#pragma unroll
            for (int mi = 0; mi < 4; mi++)
#pragma unroll
                for (int ni = 0; ni < 4; ni++) {
                    mma_f16(acc[mi][ni * 2],     af[mi], bf[ni][0], bf[ni][1]);
                    mma_f16(acc[mi][ni * 2 + 1], af[mi], bf[ni][2], bf[ni][3]);
                }
        }
    }

    const int rBase = blockIdx.y * TM + wm * 64 + (lane >> 2);
    const int cBase = blockIdx.x * TN + wn * 64 + (lane & 3) * 2;
#pragma unroll
    for (int mi = 0; mi < 4; mi++) {
#pragma unroll
        for (int ni = 0; ni < 8; ni++) {
            int row = rBase + mi * 16;
            int col = cBase + ni * 8;
            *(float2*)(g_Y + (size_t)row * NBIG + col) =
                make_float2(acc[mi][ni][0], acc[mi][ni][1]);
            *(float2*)(g_Y + (size_t)(row + 8) * NBIG + col) =
                make_float2(acc[mi][ni][2], acc[mi][ni][3]);
        }
    }
}

/* ------------------------------------------------------------------ */
/* attn tail: smem-staged q/kv, 512 threads, dynamic smem             */
/* ------------------------------------------------------------------ */
#define ATTN_THREADS 512
#define OFF_Q   0
#define OFF_KV  15360
#define OFF_XG  30720
#define OFF_H   33792
#define OFF_P   36864
#define OFF_SC  39936
#define OFF_A   40116
#define ATTN_SMEM ((40152 + 8) * 4)

__global__ void __launch_bounds__(ATTN_THREADS, 1) attn_kernel(
    const float* __restrict__ ab1, const float* __restrict__ ab2,
    const float* __restrict__ linW, const float* __restrict__ linb,
    const float* __restrict__ gb1, const float* __restrict__ gb2,
    const float* __restrict__ gW2, const float* __restrict__ prelu_a,
    const float* __restrict__ bn1g, const float* __restrict__ bn1b,
    const float* __restrict__ bn1m, const float* __restrict__ bn1v,
    const float* __restrict__ bn2g, const float* __restrict__ bn2b,
    const float* __restrict__ bn2m, const float* __restrict__ bn2v,
    float* __restrict__ out) {
    extern __shared__ float sm[];
    float* s_q  = sm + OFF_Q;    /* [30][512] : (k*6+c)*512 + m */
    float* s_kv = sm + OFF_KV;
    float* s_xg = sm + OFF_XG;   /* [6][512] */
    float* s_h  = sm + OFF_H;
    float* s_P  = sm + OFF_P;
    float* s_sc = sm + OFF_SC;   /* [30][6] */
    float* s_A  = sm + OFF_A;    /* [6][6] */

    const int b = blockIdx.x;
    const float* Yb = g_Y + (size_t)b * C_ * NBIG;
    const int tid = threadIdx.x;
    const int lane = tid & 31;
    const int w = tid >> 5;

    /* stage q+bias, kv+bias, xg */
    for (int i = tid; i < 30 * 512; i += ATTN_THREADS) {
        int kc_ = i >> 9, m = i & 511;
        int k = kc_ / 6, c = kc_ - k * 6;
        int km = k * 512 + m;
        s_q[i]  = Yb[(size_t)c * NBIG + km] + ab1[km];
        s_kv[i] = Yb[(size_t)c * NBIG + K_ * MID_ + km] + ab2[km];
    }
    for (int i = tid; i < 6 * 512; i += ATTN_THREADS)
        s_xg[i] = Yb[(size_t)(i >> 9) * NBIG + 2 * K_ * MID_ + (i & 511)];
    __syncthreads();

    /* 180 dots: warp per (k,c), registers hold q */
    for (int item = w; item < 30; item += 16) {
        int k = item / 6;
        const float4* qp = (const float4*)(s_q + (size_t)item * 512);
        float4 q0 = qp[lane], q1 = qp[lane + 32], q2 = qp[lane + 64], q3 = qp[lane + 96];
#pragma unroll
        for (int d = 0; d < 6; d++) {
            const float4* kp = (const float4*)(s_kv + (size_t)(k * 6 + d) * 512);
            float4 v0 = kp[lane], v1 = kp[lane + 32], v2 = kp[lane + 64], v3 = kp[lane + 96];
            float acc = q0.x * v0.x + q0.y * v0.y + q0.z * v0.z + q0.w * v0.w
                      + q1.x * v1.x + q1.y * v1.y + q1.z * v1.z + q1.w * v1.w
                      + q2.x * v2.x + q2.y * v2.y + q2.z * v2.z + q2.w * v2.w
                      + q3.x * v3.x + q3.y * v3.y + q3.z * v3.z + q3.w * v3.w;
#pragma unroll
            for (int o = 16; o; o >>= 1) acc += __shfl_xor_sync(0xffffffffu, acc, o);
            if (lane == 0) s_sc[item * 6 + d] = acc;
        }
    }
    __syncthreads();

    /* softmax over d */
    if (tid < 30) {
        float* r = s_sc + tid * 6;
        float mx = r[0];
#pragma unroll
        for (int d = 1; d < 6; d++) mx = fmaxf(mx, r[d]);
        float e[6], sum = 0.f;
#pragma unroll
        for (int d = 0; d < 6; d++) { e[d] = expf(r[d] - mx); sum += e[d]; }
        float inv = 1.f / sum;
#pragma unroll
        for (int d = 0; d < 6; d++) r[d] = e[d] * inv;
    }
    __syncthreads();

    /* linear exchange */
    if (tid < 36) {
        int c = tid / 6, e = tid - (tid / 6) * 6;
        float acc = linb[e];
#pragma unroll
        for (int k = 0; k < K_; k++)
#pragma unroll
            for (int d = 0; d < 6; d++)
                acc += s_sc[(k * 6 + c) * 6 + d] * linW[(k * 6 + d) * 6 + e];
        s_A[c * 6 + e] = acc;
    }
    __syncthreads();

    /* softmax -> A */
    if (tid < 6) {
        float* r = s_A + tid * 6;
        float mx = r[0];
#pragma unroll
        for (int e = 1; e < 6; e++) mx = fmaxf(mx, r[e]);
        float ev[6], sum = 0.f;
#pragma unroll
        for (int e = 0; e < 6; e++) { ev[e] = expf(r[e] - mx); sum += ev[e]; }
        float inv = 1.f / sum;
#pragma unroll
        for (int e = 0; e < 6; e++) r[e] = ev[e] * inv;
    }
    __syncthreads();

    /* GC1: h = PReLU(A@xg + gb1) -> BN1 */
    const float pa = prelu_a[0];
    for (int i = tid; i < 6 * 512; i += ATTN_THREADS) {
        int c = i >> 9, j = i & 511;
        float acc = gb1[j];
#pragma unroll
        for (int d = 0; d < 6; d++) acc += s_A[c * 6 + d] * s_xg[d * 512 + j];
        acc = acc >= 0.f ? acc : pa * acc;
        float inv = bn1g[c] * (1.f / sqrtf(bn1v[c] + 1e-5f));
        s_h[i] = (acc - bn1m[c]) * inv + bn1b[c];
    }
    __syncthreads();

    /* P = A @ h */
    for (int i = tid; i < 6 * 512; i += ATTN_THREADS) {
        int c = i >> 9, j = i & 511;
        float acc = 0.f;
#pragma unroll
        for (int d = 0; d < 6; d++) acc += s_A[c * 6 + d] * s_h[d * 512 + j];
        s_P[i] = acc;
    }
    __syncthreads();

    /* out = P @ gW2 + gb2, BN2.  (tid&255)=col, tid>>8 = j-half */
    {
        const int o = tid & 255;
        const int half = tid >> 8;
        float acc[6];
#pragma unroll
        for (int c = 0; c < 6; c++) acc[c] = half ? 0.f : gb2[o];
        const float* gp = gW2 + (size_t)(half * 256) * OUT_ + o;
#pragma unroll 8
        for (int j = 0; j < 256; j++) {
            float wv = gp[(size_t)j * OUT_];
#pragma unroll
            for (int c = 0; c < 6; c++) acc[c] += s_P[c * 512 + half * 256 + j] * wv;
        }
        if (half) {
#pragma unroll
            for (int c = 0; c < 6; c++) s_q[c * 256 + o] = acc[c];  /* s_q free now */
        }
        __syncthreads();
        if (!half) {
#pragma unroll
            for (int c = 0; c < 6; c++) {
                float v = acc[c] + s_q[c * 256 + o];
                float inv = bn2g[c] * (1.f / sqrtf(bn2v[c] + 1e-5f));
                v = (v - bn2m[c]) * inv + bn2b[c];
                out[((size_t)b * C_ + c) * OUT_ + o] = v;
            }
        }
    }
}

/* ------------------------------------------------------------------ */
extern "C" void kernel_launch(void* const* d_in, const int* in_sizes, int n_in,
                              void* d_out, int out_size) {
    const float* x       = (const float*)d_in[0];
    const float* aW1     = (const float*)d_in[1];
    const float* ab1     = (const float*)d_in[2];
    const float* aW2     = (const float*)d_in[3];
    const float* ab2     = (const float*)d_in[4];
    const float* linW    = (const float*)d_in[5];
    const float* linb    = (const float*)d_in[6];
    const float* gW1     = (const float*)d_in[7];
    const float* gb1     = (const float*)d_in[8];
    const float* gW2     = (const float*)d_in[9];
    const float* gb2     = (const float*)d_in[10];
    const float* prelu_a = (const float*)d_in[11];
    const float* bn1g    = (const float*)d_in[12];
    const float* bn1b    = (const float*)d_in[13];
    const float* bn1m    = (const float*)d_in[14];
    const float* bn1v    = (const float*)d_in[15];
    const float* bn2g    = (const float*)d_in[16];
    const float* bn2b    = (const float*)d_in[17];
    const float* bn2m    = (const float*)d_in[18];
    const float* bn2v    = (const float*)d_in[19];
    float* out = (float*)d_out;

    static bool attr_set = false;
    if (!attr_set) {
        cudaFuncSetAttribute(gemm_kernel,
                             cudaFuncAttributeMaxDynamicSharedMemorySize, SMEM_TOTAL);
        cudaFuncSetAttribute(attn_kernel,
                             cudaFuncAttributeMaxDynamicSharedMemorySize, ATTN_SMEM);
        attr_set = true;
    }

    packA_kernel<<<(MROWS / 16) * KC16 * 32 / 256, 256>>>(x);
    packB_kernel<<<(NBIG / 16) * KC16 * 32 / 256, 256>>>(aW1, aW2, gW1);

    dim3 grid(NBIG / TN, MROWS / TM);   /* 22 x 192 */
    gemm_kernel<<<grid, 256, SMEM_TOTAL>>>();

    attn_kernel<<<B_, ATTN_THREADS, ATTN_SMEM>>>(
        ab1, ab2, linW, linb, gb1, gb2, gW2, prelu_a,
        bn1g, bn1b, bn1m, bn1v, bn2g, bn2b, bn2m, bn2v, out);
}

// round 5
// speedup vs baseline: 2.6362x; 1.0921x over previous
#include <cuda_runtime.h>
#include <cuda_fp16.h>
#include <math.h>
#include <stdint.h>

#define B_    4096
#define C_    6
#define L_    1024
#define MID_  512
#define HID_  512
#define OUT_  256
#define K_    5
#define NBIG  5632            /* 2*K*MID + HID */
#define MROWS (B_ * C_)       /* 24576 */
#define KP16  3072            /* 3xFP16 augmented K */
#define KC16  192

/* big-GEMM tiling */
#define TM 128
#define TN 256
#define NSTG 48
#define ASTG_BYTES 16384
#define STG_BYTES  49152
#define SMEM_TOTAL (4 * STG_BYTES)

/* Scratch */
__device__ uint4 g_Ah[(size_t)MROWS * KP16 / 8];   /* 151 MB */
__device__ uint4 g_Bh[(size_t)NBIG * KP16 / 8];    /*  35 MB */
__device__ float g_Y[(size_t)MROWS * NBIG];        /* 554 MB */
__device__ float g_A[(size_t)B_ * 36];             /* adjacency per batch */
__device__ float g_H[(size_t)MROWS * HID_];        /* 50 MB h-stack */
__device__ float g_HG[(size_t)MROWS * OUT_];       /* 25 MB h@gW2 */

__device__ __forceinline__ uint32_t smem_u32(const void* p) {
    uint32_t a;
    asm("{ .reg .u64 t; cvta.to.shared.u64 t, %1; cvt.u32.u64 %0, t; }" : "=r"(a) : "l"(p));
    return a;
}
__device__ __forceinline__ void cpa16(uint32_t s, const void* g) {
    asm volatile("cp.async.cg.shared.global [%0], [%1], 16;" :: "r"(s), "l"(g) : "memory");
}
__device__ __forceinline__ void lds128(uint32_t* r, uint32_t a) {
    asm volatile("ld.shared.v4.b32 {%0,%1,%2,%3}, [%4];"
                 : "=r"(r[0]), "=r"(r[1]), "=r"(r[2]), "=r"(r[3]) : "r"(a));
}
__device__ __forceinline__ void mma_f16(float* c, const uint32_t* a, uint32_t b0, uint32_t b1) {
    asm volatile(
        "mma.sync.aligned.m16n8k16.row.col.f32.f16.f16.f32 "
        "{%0,%1,%2,%3}, {%4,%5,%6,%7}, {%8,%9}, {%0,%1,%2,%3};"
        : "+f"(c[0]), "+f"(c[1]), "+f"(c[2]), "+f"(c[3])
        : "r"(a[0]), "r"(a[1]), "r"(a[2]), "r"(a[3]), "r"(b0), "r"(b1));
}
__device__ __forceinline__ __half cvt_split(float x, bool lo) {
    __half hi = __float2half_rn(x);
    if (!lo) return hi;
    return __float2half_rn(x - __half2float(hi));
}

/* ------------------------- packs (unchanged) ---------------------- */
__global__ void packA_kernel(const float* __restrict__ X) {
    int cid = blockIdx.x * 256 + threadIdx.x;
    int ln = cid & 31;
    int b = cid >> 5;
    int kc = b % KC16;
    int mt = b / KC16;
    bool lo = (kc >> 6) == 1;
    int l0 = (kc & 63) * 16 + (ln & 3) * 2;
    int r0 = mt * 16 + (ln >> 2);
    float2 x00 = *(const float2*)(X + (size_t)r0 * L_ + l0);
    float2 x10 = *(const float2*)(X + (size_t)(r0 + 8) * L_ + l0);
    float2 x01 = *(const float2*)(X + (size_t)r0 * L_ + l0 + 8);
    float2 x11 = *(const float2*)(X + (size_t)(r0 + 8) * L_ + l0 + 8);
    __half h[8];
    h[0] = cvt_split(x00.x, lo); h[1] = cvt_split(x00.y, lo);
    h[2] = cvt_split(x10.x, lo); h[3] = cvt_split(x10.y, lo);
    h[4] = cvt_split(x01.x, lo); h[5] = cvt_split(x01.y, lo);
    h[6] = cvt_split(x11.x, lo); h[7] = cvt_split(x11.y, lo);
    g_Ah[cid] = *(uint4*)h;
}
__device__ __forceinline__ float fetchW(const float* aW1, const float* aW2,
                                        const float* gW1, int l, int n) {
    if (n < K_ * MID_) {
        return aW1[((size_t)(n >> 9) * L_ + l) * MID_ + (n & 511)];
    } else if (n < 2 * K_ * MID_) {
        int nn = n - K_ * MID_;
        return aW2[((size_t)(nn >> 9) * L_ + l) * MID_ + (nn & 511)];
    }
    return gW1[(size_t)l * HID_ + (n - 2 * K_ * MID_)];
}
__global__ void packB_kernel(const float* __restrict__ aW1,
                             const float* __restrict__ aW2,
                             const float* __restrict__ gW1) {
    int cid = blockIdx.x * 256 + threadIdx.x;
    int ln = cid & 31;
    int b = cid >> 5;
    int kc = b % KC16;
    int nt = b / KC16;
    bool lo = (kc >> 6) == 2;
    int l0 = (kc & 63) * 16 + (ln & 3) * 2;
    int n0 = nt * 16 + (ln >> 2);
    int n1 = n0 + 8;
    __half h[8];
    h[0] = cvt_split(fetchW(aW1, aW2, gW1, l0,     n0), lo);
    h[1] = cvt_split(fetchW(aW1, aW2, gW1, l0 + 1, n0), lo);
    h[2] = cvt_split(fetchW(aW1, aW2, gW1, l0 + 8, n0), lo);
    h[3] = cvt_split(fetchW(aW1, aW2, gW1, l0 + 9, n0), lo);
    h[4] = cvt_split(fetchW(aW1, aW2, gW1, l0,     n1), lo);
    h[5] = cvt_split(fetchW(aW1, aW2, gW1, l0 + 1, n1), lo);
    h[6] = cvt_split(fetchW(aW1, aW2, gW1, l0 + 8, n1), lo);
    h[7] = cvt_split(fetchW(aW1, aW2, gW1, l0 + 9, n1), lo);
    g_Bh[cid] = *(uint4*)h;
}

/* ------------------ big GEMM (unchanged from R4) ------------------ */
struct IssueCtx { uint32_t sb; int mtB, ntB, tid; };

__device__ __forceinline__ void issue_stage(const IssueCtx& cx, int s) {
    uint32_t stBase = cx.sb + (s & 3) * STG_BYTES;
    int kc0 = s * 4;
#pragma unroll
    for (int i = 0; i < 4; i++) {
        int cid = cx.tid + i * 256;
        int ln = cid & 31, bb = cid >> 5;
        int kci = bb >> 3, mti = bb & 7;
        uint32_t sa = stBase + (uint32_t)(((kci * 8 + mti) * 32 + ln) * 16);
        const uint4* ga = g_Ah + ((size_t)(cx.mtB + mti) * KC16 + kc0 + kci) * 32 + ln;
        cpa16(sa, ga);
    }
#pragma unroll
    for (int i = 0; i < 8; i++) {
        int cid = cx.tid + i * 256;
        int ln = cid & 31, bb = cid >> 5;
        int kci = bb >> 4, nti = bb & 15;
        uint32_t sb2 = stBase + ASTG_BYTES + (uint32_t)(((kci * 16 + nti) * 32 + ln) * 16);
        const uint4* gb = g_Bh + ((size_t)(cx.ntB + nti) * KC16 + kc0 + kci) * 32 + ln;
        cpa16(sb2, gb);
    }
    asm volatile("cp.async.commit_group;" ::: "memory");
}

__global__ void __launch_bounds__(256, 1) gemm_kernel() {
    extern __shared__ char smem[];
    const uint32_t sb = smem_u32(smem);
    const int tid = threadIdx.x;
    const int lane = tid & 31;
    const int wid = tid >> 5;
    const int wm = wid & 1;
    const int wn = wid >> 1;
    const int mtB = blockIdx.y * 8;
    const int ntB = blockIdx.x * 16;

    IssueCtx cx{sb, mtB, ntB, tid};

    float acc[4][8][4];
#pragma unroll
    for (int a = 0; a < 4; a++)
#pragma unroll
        for (int bq = 0; bq < 8; bq++)
#pragma unroll
            for (int c = 0; c < 4; c++) acc[a][bq][c] = 0.f;

    issue_stage(cx, 0);
    issue_stage(cx, 1);
    issue_stage(cx, 2);

    for (int s = 0; s < NSTG; s++) {
        asm volatile("cp.async.wait_group 2;" ::: "memory");
        __syncthreads();
        if (s + 3 < NSTG) issue_stage(cx, s + 3);
        else asm volatile("cp.async.commit_group;" ::: "memory");

        uint32_t stBase = sb + (s & 3) * STG_BYTES;
#pragma unroll
        for (int kc = 0; kc < 4; kc++) {
            uint32_t af[4][4], bf[4][4];
#pragma unroll
            for (int mi = 0; mi < 4; mi++)
                lds128(af[mi], stBase + (uint32_t)((((kc * 8) + wm * 4 + mi) * 32 + lane) * 16));
#pragma unroll
            for (int ni = 0; ni < 4; ni++)
                lds128(bf[ni], stBase + ASTG_BYTES +
                               (uint32_t)((((kc * 16) + wn * 4 + ni) * 32 + lane) * 16));
#pragma unroll
            for (int mi = 0; mi < 4; mi++)
#pragma unroll
                for (int ni = 0; ni < 4; ni++) {
                    mma_f16(acc[mi][ni * 2],     af[mi], bf[ni][0], bf[ni][1]);
                    mma_f16(acc[mi][ni * 2 + 1], af[mi], bf[ni][2], bf[ni][3]);
                }
        }
    }

    const int rBase = blockIdx.y * TM + wm * 64 + (lane >> 2);
    const int cBase = blockIdx.x * TN + wn * 64 + (lane & 3) * 2;
#pragma unroll
    for (int mi = 0; mi < 4; mi++) {
#pragma unroll
        for (int ni = 0; ni < 8; ni++) {
            int row = rBase + mi * 16;
            int col = cBase + ni * 8;
            *(float2*)(g_Y + (size_t)row * NBIG + col) =
                make_float2(acc[mi][ni][0], acc[mi][ni][1]);
            *(float2*)(g_Y + (size_t)(row + 8) * NBIG + col) =
                make_float2(acc[mi][ni][2], acc[mi][ni][3]);
        }
    }
}

/* ------------------------------------------------------------------ */
/* score_kernel: CTA per batch, 5 warps (one per head k).             */
/* kv rows in registers; streams q rows; -> adjacency A (6x6)         */
/* ------------------------------------------------------------------ */
__global__ void __launch_bounds__(160) score_kernel(
    const float* __restrict__ ab1, const float* __restrict__ ab2,
    const float* __restrict__ linW, const float* __restrict__ linb) {
    const int b = blockIdx.x;
    const int tid = threadIdx.x;
    const int lane = tid & 31;
    const int k = tid >> 5;
    const float* Yb = g_Y + (size_t)b * C_ * NBIG;

    __shared__ float s_sc[K_ * 36];
    __shared__ float s_l[36];

    /* bias chunks for this (k, lane) */
    float b2[16], b1[16];
#pragma unroll
    for (int it = 0; it < 4; it++) {
        float4 v2 = *(const float4*)(ab2 + k * MID_ + it * 128 + lane * 4);
        float4 v1 = *(const float4*)(ab1 + k * MID_ + it * 128 + lane * 4);
        b2[it*4] = v2.x; b2[it*4+1] = v2.y; b2[it*4+2] = v2.z; b2[it*4+3] = v2.w;
        b1[it*4] = v1.x; b1[it*4+1] = v1.y; b1[it*4+2] = v1.z; b1[it*4+3] = v1.w;
    }

    /* kv rows (6) resident in registers, bias-corrected */
    float kv[6][16];
#pragma unroll
    for (int d = 0; d < 6; d++) {
        const float* kp = Yb + (size_t)d * NBIG + K_ * MID_ + k * MID_;
#pragma unroll
        for (int it = 0; it < 4; it++) {
            float4 v = *(const float4*)(kp + it * 128 + lane * 4);
            kv[d][it*4]   = v.x + b2[it*4];
            kv[d][it*4+1] = v.y + b2[it*4+1];
            kv[d][it*4+2] = v.z + b2[it*4+2];
            kv[d][it*4+3] = v.w + b2[it*4+3];
        }
    }

    /* stream q rows; 6 dots each; softmax over d on lane 0 */
#pragma unroll
    for (int c = 0; c < 6; c++) {
        float q[16];
        const float* qp = Yb + (size_t)c * NBIG + k * MID_;
#pragma unroll
        for (int it = 0; it < 4; it++) {
            float4 v = *(const float4*)(qp + it * 128 + lane * 4);
            q[it*4]   = v.x + b1[it*4];
            q[it*4+1] = v.y + b1[it*4+1];
            q[it*4+2] = v.z + b1[it*4+2];
            q[it*4+3] = v.w + b1[it*4+3];
        }
        float acc[6];
#pragma unroll
        for (int d = 0; d < 6; d++) {
            float a = 0.f;
#pragma unroll
            for (int m = 0; m < 16; m++) a += q[m] * kv[d][m];
            acc[d] = a;
        }
#pragma unroll
        for (int o = 16; o; o >>= 1)
#pragma unroll
            for (int d = 0; d < 6; d++) acc[d] += __shfl_xor_sync(0xffffffffu, acc[d], o);
        if (lane == 0) {
            float mx = acc[0];
#pragma unroll
            for (int d = 1; d < 6; d++) mx = fmaxf(mx, acc[d]);
            float e[6], sum = 0.f;
#pragma unroll
            for (int d = 0; d < 6; d++) { e[d] = expf(acc[d] - mx); sum += e[d]; }
            float inv = 1.f / sum;
#pragma unroll
            for (int d = 0; d < 6; d++) s_sc[k * 36 + c * 6 + d] = e[d] * inv;
        }
    }
    __syncthreads();

    /* linear exchange */
    if (tid < 36) {
        int c = tid / 6, e = tid - (tid / 6) * 6;
        float acc = linb[e];
#pragma unroll
        for (int k2 = 0; k2 < K_; k2++)
#pragma unroll
            for (int d = 0; d < 6; d++)
                acc += s_sc[k2 * 36 + c * 6 + d] * linW[(k2 * 6 + d) * 6 + e];
        s_l[tid] = acc;
    }
    __syncthreads();

    /* softmax rows -> g_A */
    if (tid < 6) {
        float* r = s_l + tid * 6;
        float mx = r[0];
#pragma unroll
        for (int e = 1; e < 6; e++) mx = fmaxf(mx, r[e]);
        float ev[6], sum = 0.f;
#pragma unroll
        for (int e = 0; e < 6; e++) { ev[e] = expf(r[e] - mx); sum += ev[e]; }
        float inv = 1.f / sum;
        float* ap = g_A + (size_t)b * 36 + tid * 6;
#pragma unroll
        for (int e = 0; e < 6; e++) ap[e] = ev[e] * inv;
    }
}

/* ------------------------------------------------------------------ */
/* h_kernel: g_H[r, :] = BN1(PReLU(sum_d A[c,d] xg[b,d,:] + gb1))     */
/* one thread per float4                                              */
/* ------------------------------------------------------------------ */
__global__ void __launch_bounds__(256) h_kernel(
    const float* __restrict__ gb1, const float* __restrict__ prelu_a,
    const float* __restrict__ bn1g, const float* __restrict__ bn1b,
    const float* __restrict__ bn1m, const float* __restrict__ bn1v) {
    int idx = blockIdx.x * 256 + threadIdx.x;      /* < 24576*128 */
    int j4 = idx & 127;
    int r = idx >> 7;
    int b = r / 6;
    int c = r - b * 6;
    const float* Ab = g_A + (size_t)b * 36 + c * 6;
    float a0 = Ab[0], a1 = Ab[1], a2 = Ab[2], a3 = Ab[3], a4 = Ab[4], a5 = Ab[5];
    const float* xg = g_Y + (size_t)b * 6 * NBIG + 2 * K_ * MID_ + j4 * 4;
    float4 z = *(const float4*)(gb1 + j4 * 4);
    float4 v;
#define ACC4(aa, d) \
    v = *(const float4*)(xg + (size_t)(d) * NBIG); \
    z.x += (aa) * v.x; z.y += (aa) * v.y; z.z += (aa) * v.z; z.w += (aa) * v.w;
    ACC4(a0, 0) ACC4(a1, 1) ACC4(a2, 2) ACC4(a3, 3) ACC4(a4, 4) ACC4(a5, 5)
#undef ACC4
    float pa = prelu_a[0];
    z.x = z.x >= 0.f ? z.x : pa * z.x;
    z.y = z.y >= 0.f ? z.y : pa * z.y;
    z.z = z.z >= 0.f ? z.z : pa * z.z;
    z.w = z.w >= 0.f ? z.w : pa * z.w;
    float inv = bn1g[c] * (1.f / sqrtf(bn1v[c] + 1e-5f));
    float mu = bn1m[c], bb = bn1b[c];
    z.x = (z.x - mu) * inv + bb;
    z.y = (z.y - mu) * inv + bb;
    z.z = (z.z - mu) * inv + bb;
    z.w = (z.w - mu) * inv + bb;
    *(float4*)(g_H + (size_t)r * HID_ + j4 * 4) = z;
}

/* ------------------------------------------------------------------ */
/* hg SGEMM: g_HG(24576x256) = g_H(24576x512) @ gW2(512x256), fp32    */
/* ------------------------------------------------------------------ */
#define SBM 128
#define SBN 128
#define SBK 16
__global__ void __launch_bounds__(256, 2) hg_gemm_kernel(const float* __restrict__ gW2) {
    __shared__ float As[SBK][SBM];
    __shared__ float Bs[SBK][SBN];
    const int bx = blockIdx.x;   /* 0..1 */
    const int by = blockIdx.y;   /* 0..191 */
    const int tid = threadIdx.x;
    const int tx = tid & 15;
    const int ty = tid >> 4;
    const int a_row = tid >> 2;
    const int a_col = (tid & 3) << 2;
    const int b_row = tid >> 5;
    const int b_col = (tid & 31) << 2;
    const float* Ab = g_H + (size_t)(by * SBM) * HID_;
    const float* Bb = gW2 + bx * SBN;

    float acc[8][8];
#pragma unroll
    for (int i = 0; i < 8; i++)
#pragma unroll
        for (int j = 0; j < 8; j++) acc[i][j] = 0.f;

    for (int k0 = 0; k0 < HID_; k0 += SBK) {
#pragma unroll
        for (int i = 0; i < 2; i++) {
            int r = a_row + i * 64;
            float4 v = *(const float4*)(Ab + (size_t)r * HID_ + k0 + a_col);
            As[a_col + 0][r] = v.x;
            As[a_col + 1][r] = v.y;
            As[a_col + 2][r] = v.z;
            As[a_col + 3][r] = v.w;
        }
#pragma unroll
        for (int i = 0; i < 2; i++) {
            int r = b_row + i * 8;
            *(float4*)&Bs[r][b_col] =
                *(const float4*)(Bb + (size_t)(k0 + r) * OUT_ + b_col);
        }
        __syncthreads();
#pragma unroll
        for (int kk = 0; kk < SBK; kk++) {
            float4 a0 = *(const float4*)&As[kk][ty * 8];
            float4 a1 = *(const float4*)&As[kk][ty * 8 + 4];
            float4 b0 = *(const float4*)&Bs[kk][tx * 8];
            float4 b1 = *(const float4*)&Bs[kk][tx * 8 + 4];
            float ar[8] = {a0.x, a0.y, a0.z, a0.w, a1.x, a1.y, a1.z, a1.w};
            float br[8] = {b0.x, b0.y, b0.z, b0.w, b1.x, b1.y, b1.z, b1.w};
#pragma unroll
            for (int i = 0; i < 8; i++)
#pragma unroll
                for (int j = 0; j < 8; j++) acc[i][j] += ar[i] * br[j];
        }
        __syncthreads();
    }
    float* Cp = g_HG + (size_t)(by * SBM + ty * 8) * OUT_ + bx * SBN + tx * 8;
#pragma unroll
    for (int i = 0; i < 8; i++)
#pragma unroll
        for (int j = 0; j < 8; j += 4)
            *(float4*)(Cp + (size_t)i * OUT_ + j) =
                make_float4(acc[i][j], acc[i][j+1], acc[i][j+2], acc[i][j+3]);
}

/* ------------------------------------------------------------------ */
/* out_kernel: out[b,c,o] = BN2(sum_d A[c,d] hg[b,d,o] + gb2[o])      */
/* ------------------------------------------------------------------ */
__global__ void __launch_bounds__(256) out_kernel(
    const float* __restrict__ gb2,
    const float* __restrict__ bn2g, const float* __restrict__ bn2b,
    const float* __restrict__ bn2m, const float* __restrict__ bn2v,
    float* __restrict__ out) {
    const int b = blockIdx.x;
    const int o = threadIdx.x;
    __shared__ float sA[36];
    if (o < 36) sA[o] = g_A[(size_t)b * 36 + o];
    __syncthreads();
    float hgv[6];
#pragma unroll
    for (int d = 0; d < 6; d++)
        hgv[d] = g_HG[((size_t)b * 6 + d) * OUT_ + o];
    float g2 = gb2[o];
#pragma unroll
    for (int c = 0; c < 6; c++) {
        float acc = g2;
#pragma unroll
        for (int d = 0; d < 6; d++) acc += sA[c * 6 + d] * hgv[d];
        float inv = bn2g[c] * (1.f / sqrtf(bn2v[c] + 1e-5f));
        acc = (acc - bn2m[c]) * inv + bn2b[c];
        out[((size_t)b * C_ + c) * OUT_ + o] = acc;
    }
}

/* ------------------------------------------------------------------ */
extern "C" void kernel_launch(void* const* d_in, const int* in_sizes, int n_in,
                              void* d_out, int out_size) {
    const float* x       = (const float*)d_in[0];
    const float* aW1     = (const float*)d_in[1];
    const float* ab1     = (const float*)d_in[2];
    const float* aW2     = (const float*)d_in[3];
    const float* ab2     = (const float*)d_in[4];
    const float* linW    = (const float*)d_in[5];
    const float* linb    = (const float*)d_in[6];
    const float* gW1     = (const float*)d_in[7];
    const float* gb1     = (const float*)d_in[8];
    const float* gW2     = (const float*)d_in[9];
    const float* gb2     = (const float*)d_in[10];
    const float* prelu_a = (const float*)d_in[11];
    const float* bn1g    = (const float*)d_in[12];
    const float* bn1b    = (const float*)d_in[13];
    const float* bn1m    = (const float*)d_in[14];
    const float* bn1v    = (const float*)d_in[15];
    const float* bn2g    = (const float*)d_in[16];
    const float* bn2b    = (const float*)d_in[17];
    const float* bn2m    = (const float*)d_in[18];
    const float* bn2v    = (const float*)d_in[19];
    float* out = (float*)d_out;

    static bool attr_set = false;
    if (!attr_set) {
        cudaFuncSetAttribute(gemm_kernel,
                             cudaFuncAttributeMaxDynamicSharedMemorySize, SMEM_TOTAL);
        attr_set = true;
    }

    packA_kernel<<<(MROWS / 16) * KC16 * 32 / 256, 256>>>(x);
    packB_kernel<<<(NBIG / 16) * KC16 * 32 / 256, 256>>>(aW1, aW2, gW1);

    dim3 grid(NBIG / TN, MROWS / TM);
    gemm_kernel<<<grid, 256, SMEM_TOTAL>>>();

    score_kernel<<<B_, 160>>>(ab1, ab2, linW, linb);
    h_kernel<<<MROWS * (HID_ / 4) / 256, 256>>>(gb1, prelu_a, bn1g, bn1b, bn1m, bn1v);
    {
        dim3 g2(OUT_ / SBN, MROWS / SBM);   /* 2 x 192 */
        hg_gemm_kernel<<<g2, 256>>>(gW2);
    }
    out_kernel<<<B_, OUT_>>>(gb2, bn2g, bn2b, bn2m, bn2v, out);
}